// round 11
// baseline (speedup 1.0000x reference)
#include <cuda_runtime.h>
#include <cuda_bf16.h>
#include <math.h>
#include <stdint.h>

// ---------------------------------------------------------------------------
// Swin block: B=32,H=W=56,C=192,NH=6,WS=7,SS=3,HD=32,N=49,MLP_H=768
// GEMMs + attention via mma.sync m16n8k16 bf16, ldmatrix, 3-stage cp.async.
// Proj GEMM fuses bias + residual + LayerNorm2 epilogue (full-row tiles).
// ---------------------------------------------------------------------------

#define Bn     32
#define Hh     56
#define Ww     56
#define Cc     192
#define NHh    6
#define WSs    7
#define SSs    3
#define HDd    32
#define Nn     49
#define MLPH   768
#define Ltok   (Hh*Ww)
#define TOT    (Bn*Ltok)          // 100352
#define NWIN   2048
#define SCALEF 0.17677669529663687f

// GEMM tiling: CTA 128x192, K-chunk 32, 3 stages, 16 warps (4M x 4N), warp 32x48.
#define GBM   128
#define GBN   192
#define GBK   32
#define PITCH 40                    // bf16 units per smem row (80B)
#define A_ST  (GBM*PITCH)           // 5120 bf16 = 10240 B / stage
#define B_ST  (GBN*PITCH)           // 7680 bf16 = 15360 B / stage
#define GSMEM ((3*A_ST + 3*B_ST) * 2)   // 76800 B (LN stage 51200B reuses this)

typedef __nv_bfloat16 bf16;
typedef __nv_bfloat162 bf162;

// ------------------------- scratch (device globals) ------------------------
__device__ bf16  g_XW [TOT * Cc];
__device__ bf16  g_QKV[TOT * 3 * Cc];
__device__ bf16  g_ATT[TOT * Cc];
__device__ float g_XR [TOT * Cc];
__device__ bf16  g_XN2[TOT * Cc];
__device__ bf16  g_H  [TOT * MLPH];
__device__ bf16  g_Wq [576 * Cc];
__device__ bf16  g_Wp [Cc * Cc];
__device__ bf16  g_W1 [MLPH * Cc];
__device__ bf16  g_W2 [Cc * MLPH];
__device__ float g_BM [4 * NHh * 64 * 64];

// --------------------------- PTX helpers -----------------------------------
__device__ __forceinline__ uint32_t smem_u32(const void* p) {
    uint32_t a;
    asm("{ .reg .u64 t; cvta.to.shared.u64 t, %1; cvt.u32.u64 %0, t; }"
        : "=r"(a) : "l"(p));
    return a;
}

#define CP_ASYNC16(dst, src) \
    asm volatile("cp.async.cg.shared.global [%0], [%1], 16;" :: "r"(dst), "l"(src))
#define CP_COMMIT() asm volatile("cp.async.commit_group;")
#define CP_WAIT(n)  asm volatile("cp.async.wait_group %0;" :: "n"(n))

__device__ __forceinline__ void mma_bf16(float* c, const uint32_t* a, const uint32_t* b) {
    asm volatile(
        "mma.sync.aligned.m16n8k16.row.col.f32.bf16.bf16.f32 "
        "{%0,%1,%2,%3}, {%4,%5,%6,%7}, {%8,%9}, {%0,%1,%2,%3};"
        : "+f"(c[0]), "+f"(c[1]), "+f"(c[2]), "+f"(c[3])
        : "r"(a[0]), "r"(a[1]), "r"(a[2]), "r"(a[3]), "r"(b[0]), "r"(b[1]));
}

__device__ __forceinline__ void ldsm_x4(uint32_t* r, uint32_t addr) {
    asm volatile("ldmatrix.sync.aligned.m8n8.x4.shared.b16 {%0,%1,%2,%3}, [%4];"
                 : "=r"(r[0]), "=r"(r[1]), "=r"(r[2]), "=r"(r[3]) : "r"(addr));
}

__device__ __forceinline__ uint32_t packbf(float lo, float hi) {
    uint32_t r;
    asm("cvt.rn.bf16x2.f32 %0, %1, %2;" : "=r"(r) : "f"(hi), "f"(lo));
    return r;
}

// --------------------- token <-> (shifted window) mapping ------------------
__device__ __forceinline__ int win_to_tok(int t) {
    int win = t / Nn, r = t - win * Nn;
    int b = win >> 6, w_ = win & 63;
    int wh = w_ >> 3, ww = w_ & 7;
    int ih = r / WSs, iw = r - ih * WSs;
    int rr = wh * WSs + ih + SSs; if (rr >= Hh) rr -= Hh;
    int cc = ww * WSs + iw + SSs; if (cc >= Ww) cc -= Ww;
    return b * Ltok + rr * Ww + cc;
}

// ----------------------- weight conversion to bf16 --------------------------
__global__ void wconv_kernel(const float* __restrict__ qw, const float* __restrict__ pw,
                             const float* __restrict__ w1, const float* __restrict__ w2) {
    int i = blockIdx.x * blockDim.x + threadIdx.x;
    if (i < 576 * Cc)  g_Wq[i] = __float2bfloat16(qw[i]);
    if (i < Cc * Cc)   g_Wp[i] = __float2bfloat16(pw[i]);
    if (i < MLPH * Cc) g_W1[i] = __float2bfloat16(w1[i]);
    if (i < Cc * MLPH) g_W2[i] = __float2bfloat16(w2[i]);
}

// -------------------- bias + shift-mask table init -------------------------
__global__ void bm_init_kernel(const float* __restrict__ tbl) {
    int idx = blockIdx.x * blockDim.x + threadIdx.x;
    if (idx >= 4 * NHh * 64 * 64) return;
    int j = idx & 63, i = (idx >> 6) & 63;
    int hh = (idx >> 12) % NHh, wt = (idx >> 12) / NHh;
    float v;
    if (i < Nn && j < Nn) {
        int ih = i / 7, iw = i % 7, jh = j / 7, jw = j % 7;
        int ridx = (ih - jh + 6) * 13 + (iw - jw + 6);
        v = tbl[ridx * NHh + hh];
        int th = wt >> 1, tw = wt & 1;
        int li = (th ? (ih < 4 ? 1 : 2) : 0) * 3 + (tw ? (iw < 4 ? 1 : 2) : 0);
        int lj = (th ? (jh < 4 ? 1 : 2) : 0) * 3 + (tw ? (jw < 4 ? 1 : 2) : 0);
        if (li != lj) v -= 100.f;
    } else {
        v = -1e30f;
    }
    g_BM[idx] = v;
}

// --------------------------- LN1 kernel -------------------------------------
__global__ void ln1_gather_kernel(const float* __restrict__ x,
                                  const float* __restrict__ g,
                                  const float* __restrict__ bt) {
    int warp = (blockIdx.x * blockDim.x + threadIdx.x) >> 5;
    int lane = threadIdx.x & 31;
    if (warp >= TOT) return;
    const float* src = x + (size_t)win_to_tok(warp) * Cc;
    float v[6], s = 0.f, ss = 0.f;
#pragma unroll
    for (int k = 0; k < 6; k++) { v[k] = src[lane + k * 32]; s += v[k]; ss += v[k] * v[k]; }
#pragma unroll
    for (int o = 16; o; o >>= 1) {
        s  += __shfl_xor_sync(0xffffffffu, s, o);
        ss += __shfl_xor_sync(0xffffffffu, ss, o);
    }
    float mu = s * (1.f / Cc);
    float rstd = rsqrtf(ss * (1.f / Cc) - mu * mu + 1e-5f);
    bf16* dst = g_XW + (size_t)warp * Cc;
#pragma unroll
    for (int k = 0; k < 6; k++) {
        int c = lane + k * 32;
        dst[c] = __float2bfloat16((v[k] - mu) * rstd * g[c] + bt[c]);
    }
}

// --------------------------- bf16 mma GEMM ----------------------------------
// C[M,Nd] = A[M,KK] * W[Nd,KK]^T.  CTA 128x192, 16 warps 4(M)x4(N), warp 32x48.
// BK=32, 3-stage cp.async, ldmatrix loads.
// EPI: 0 plain->bf16, 1 proj: bias + residual(x) + LN2 -> XR(fp32)+g_XN2(bf16),
//      2 bias+gelu->bf16, 3 bias+residual->fp32.
template <int EPI, int KK>
__global__ __launch_bounds__(512)
void gemm_mma(const bf16* __restrict__ A, const bf16* __restrict__ W,
              const float* __restrict__ bias, const float* __restrict__ res,
              void* __restrict__ outp, int Nd,
              const float* __restrict__ g2, const float* __restrict__ b2) {
    constexpr int NC = KK / GBK;
    extern __shared__ __align__(16) bf16 smem[];
    uint32_t a_st[3], b_st[3];
#pragma unroll
    for (int s = 0; s < 3; ++s) {
        a_st[s] = smem_u32(smem + s * A_ST);
        b_st[s] = smem_u32(smem + 3 * A_ST + s * B_ST);
    }

    const int tid = threadIdx.x;
    const int wid = tid >> 5;
    const int lane = tid & 31;
    const int gr = lane >> 2, gc = lane & 3;
    const int wm = wid >> 2;          // 0..3 (32 rows each)
    const int wn = wid & 3;           // 0..3 (48 cols each)
    const int mbase = blockIdx.x * GBM;
    const int nbase = blockIdx.y * GBN;

    const bf16* Ab = A + (size_t)mbase * KK;
    const bf16* Wb = W + (size_t)nbase * KK;

    const int rA = wm * 32 + (lane & 15);
    const int cA = (lane >> 4) << 3;
    const int rB = wn * 48 + (lane & 7) + ((lane >> 4) << 3);
    const int cB = ((lane >> 3) & 1) << 3;

    float acc[2][6][4];
#pragma unroll
    for (int i = 0; i < 2; i++)
#pragma unroll
        for (int j = 0; j < 6; j++)
#pragma unroll
            for (int k = 0; k < 4; k++) acc[i][j][k] = 0.f;

#define LOAD_CHUNK(sidx, cidx)                                                  \
    do {                                                                        \
        const int koff = (cidx) * GBK;                                          \
        {                                                                       \
            int row = tid >> 2, seg = tid & 3;                                  \
            CP_ASYNC16(a_st[sidx] + (uint32_t)(row * 80 + seg * 16),            \
                       Ab + (size_t)row * KK + koff + seg * 8);                 \
        }                                                                       \
        _Pragma("unroll")                                                       \
        for (int i = tid; i < GBN * 4; i += 512) {                              \
            int row = i >> 2, seg = i & 3;                                      \
            CP_ASYNC16(b_st[sidx] + (uint32_t)(row * 80 + seg * 16),            \
                       Wb + (size_t)row * KK + koff + seg * 8);                 \
        }                                                                       \
        CP_COMMIT();                                                            \
    } while (0)

    LOAD_CHUNK(0, 0);
    LOAD_CHUNK(1, 1);

    int sc = 0;
    for (int c = 0; c < NC; ++c) {
        CP_WAIT(1);
        __syncthreads();
        if (c + 2 < NC) {
            int sn = sc + 2; if (sn >= 3) sn -= 3;
            LOAD_CHUNK(sn, c + 2);
        }
        const uint32_t ab = a_st[sc];
        const uint32_t bb = b_st[sc];
#pragma unroll
        for (int ks = 0; ks < 2; ++ks) {
            const int kk = ks * 16;
            uint32_t af[2][4], bq[3][4];
#pragma unroll
            for (int mt = 0; mt < 2; ++mt)
                ldsm_x4(af[mt], ab + (uint32_t)((rA + mt * 16) * PITCH + kk + cA) * 2);
#pragma unroll
            for (int nt2 = 0; nt2 < 3; ++nt2)
                ldsm_x4(bq[nt2], bb + (uint32_t)((rB + nt2 * 16) * PITCH + kk + cB) * 2);
#pragma unroll
            for (int mt = 0; mt < 2; ++mt)
#pragma unroll
                for (int nt2 = 0; nt2 < 3; ++nt2) {
                    mma_bf16(acc[mt][nt2 * 2 + 0], af[mt], &bq[nt2][0]);
                    mma_bf16(acc[mt][nt2 * 2 + 1], af[mt], &bq[nt2][2]);
                }
        }
        if (++sc == 3) sc = 0;
    }
#undef LOAD_CHUNK

    // ----------------------- epilogues --------------------------------------
    if (EPI == 1) {
        // proj: bias -> smem stage (64 rows/pass), + residual x, LN2,
        // write XR (fp32, outp) and g_XN2 (bf16), rows scattered via win_to_tok.
        float* stg = (float*)smem;     // 64 x 200 floats = 51200 B
#pragma unroll
        for (int pass = 0; pass < 2; ++pass) {
            __syncthreads();
            if ((wm >> 1) == pass) {
                const int rbase = (wm & 1) * 32;
#pragma unroll
                for (int mt = 0; mt < 2; ++mt)
#pragma unroll
                    for (int half = 0; half < 2; ++half) {
                        int r64 = rbase + mt * 16 + gr + half * 8;
#pragma unroll
                        for (int nj = 0; nj < 6; ++nj) {
                            int col = wn * 48 + (nj >> 1) * 16 + (nj & 1) * 8 + gc * 2;
                            stg[r64 * 200 + col]     = acc[mt][nj][half * 2]     + bias[col];
                            stg[r64 * 200 + col + 1] = acc[mt][nj][half * 2 + 1] + bias[col + 1];
                        }
                    }
            }
            __syncthreads();
#pragma unroll
            for (int it = 0; it < 4; ++it) {
                int r64 = wid * 4 + it;
                int tok = win_to_tok(mbase + pass * 64 + r64);
                const float* xr = res + (size_t)tok * Cc;
                float v[6], s = 0.f, ss = 0.f;
#pragma unroll
                for (int k = 0; k < 6; ++k) {
                    int ccol = lane + k * 32;
                    v[k] = stg[r64 * 200 + ccol] + xr[ccol];
                    s += v[k]; ss += v[k] * v[k];
                }
#pragma unroll
                for (int o = 16; o; o >>= 1) {
                    s  += __shfl_xor_sync(0xffffffffu, s, o);
                    ss += __shfl_xor_sync(0xffffffffu, ss, o);
                }
                float mu = s * (1.f / Cc);
                float rstd = rsqrtf(ss * (1.f / Cc) - mu * mu + 1e-5f);
                float* xrow = (float*)outp + (size_t)tok * Cc;
                bf16* nrow = g_XN2 + (size_t)tok * Cc;
#pragma unroll
                for (int k = 0; k < 6; ++k) {
                    int ccol = lane + k * 32;
                    xrow[ccol] = v[k];
                    nrow[ccol] = __float2bfloat16((v[k] - mu) * rstd * g2[ccol] + b2[ccol]);
                }
            }
        }
    } else {
#pragma unroll
        for (int mt = 0; mt < 2; ++mt) {
#pragma unroll
            for (int half = 0; half < 2; ++half) {
                int row = mbase + wm * 32 + mt * 16 + gr + half * 8;
#pragma unroll
                for (int nj = 0; nj < 6; ++nj) {
                    int col = nbase + wn * 48 + (nj >> 1) * 16 + (nj & 1) * 8 + gc * 2;
                    float v0 = acc[mt][nj][half * 2 + 0];
                    float v1 = acc[mt][nj][half * 2 + 1];
                    if (EPI == 0) {
                        *(uint32_t*)((bf16*)outp + (size_t)row * Nd + col) = packbf(v0, v1);
                    } else if (EPI == 2) {
                        float a0 = v0 + bias[col], a1 = v1 + bias[col + 1];
                        const float kc = 0.70710678118654752f;
                        *(uint32_t*)((bf16*)outp + (size_t)row * Nd + col) =
                            packbf(0.5f * a0 * (1.f + erff(a0 * kc)),
                                   0.5f * a1 * (1.f + erff(a1 * kc)));
                    } else { // EPI == 3
                        const float* rp = res + (size_t)row * Nd + col;
                        float2 o = make_float2(v0 + bias[col] + rp[0],
                                               v1 + bias[col + 1] + rp[1]);
                        *(float2*)((float*)outp + (size_t)row * Nd + col) = o;
                    }
                }
            }
        }
    }
}

// --------------------------- mma attention ----------------------------------
#define ATTN_SMEM_BYTES (6 * 3712 * 4)   // 89088

__global__ __launch_bounds__(384, 1)
void attn_mma_kernel() {
    extern __shared__ uint32_t sm32[];
    const int tid = threadIdx.x;
    const int win = blockIdx.x;
    const int h = tid >> 6;
    const int t2 = tid & 63;

    uint32_t* Qs = sm32 + h * 3712;
    uint32_t* Ks = Qs + 1280;
    uint32_t* Vt = Ks + 1280;

    for (int i = t2; i < 3712; i += 64) Qs[i] = 0;
    __syncthreads();

    const uint32_t* qkv = (const uint32_t*)g_QKV + (size_t)win * Nn * 288;
    bf16* vtb = (bf16*)Vt;
    for (int i = t2; i < Nn * 16; i += 64) {
        int row = i >> 4, wd = i & 15;
        const uint32_t* tp = qkv + row * 288 + h * 16 + wd;
        Qs[row * 20 + wd] = tp[0];
        Ks[row * 20 + wd] = tp[96];
        uint32_t vv = tp[192];
        bf162 v2 = *(bf162*)&vv;
        vtb[(2 * wd) * 72 + row]     = v2.x;
        vtb[(2 * wd + 1) * 72 + row] = v2.y;
    }
    __syncthreads();

    const int w = tid >> 5;
    const int lane = tid & 31;
    const int gr = lane >> 2, gc = lane & 3;
    const int qb = (w & 1) * 32;
    const int wh = (win & 63) >> 3, ww = win & 7;
    const int wt = ((wh == 7) ? 2 : 0) + ((ww == 7) ? 1 : 0);
    const float* bmp = g_BM + ((size_t)(wt * NHh + h) << 12);

    float sacc[2][8][4];
#pragma unroll
    for (int a = 0; a < 2; a++)
#pragma unroll
        for (int b = 0; b < 8; b++)
#pragma unroll
            for (int cse = 0; cse < 4; cse++) sacc[a][b][cse] = 0.f;

#pragma unroll
    for (int kst = 0; kst < 2; ++kst) {
        uint32_t af[2][4], bfr[8][2];
#pragma unroll
        for (int mt = 0; mt < 2; ++mt) {
            int r = qb + mt * 16 + gr;
            af[mt][0] = Qs[r * 20 + kst * 8 + gc];
            af[mt][1] = Qs[(r + 8) * 20 + kst * 8 + gc];
            af[mt][2] = Qs[r * 20 + kst * 8 + gc + 4];
            af[mt][3] = Qs[(r + 8) * 20 + kst * 8 + gc + 4];
        }
#pragma unroll
        for (int nt = 0; nt < 8; ++nt) {
            int j = nt * 8 + gr;
            bfr[nt][0] = Ks[j * 20 + kst * 8 + gc];
            bfr[nt][1] = Ks[j * 20 + kst * 8 + gc + 4];
        }
#pragma unroll
        for (int mt = 0; mt < 2; ++mt)
#pragma unroll
            for (int nt = 0; nt < 8; ++nt)
                mma_bf16(sacc[mt][nt], af[mt], bfr[nt]);
    }

    float invr[2][2];
#pragma unroll
    for (int mt = 0; mt < 2; ++mt) {
#pragma unroll
        for (int hf = 0; hf < 2; ++hf) {
            int row = qb + mt * 16 + gr + hf * 8;
            const float* bmr = bmp + row * 64 + 2 * gc;
            float v[8][2], mx = -3e38f;
#pragma unroll
            for (int nt = 0; nt < 8; ++nt) {
                float2 bm2 = *(const float2*)(bmr + nt * 8);
                v[nt][0] = sacc[mt][nt][hf * 2 + 0] * SCALEF + bm2.x;
                v[nt][1] = sacc[mt][nt][hf * 2 + 1] * SCALEF + bm2.y;
                mx = fmaxf(mx, fmaxf(v[nt][0], v[nt][1]));
            }
            mx = fmaxf(mx, __shfl_xor_sync(0xffffffffu, mx, 1));
            mx = fmaxf(mx, __shfl_xor_sync(0xffffffffu, mx, 2));
            float sum = 0.f;
#pragma unroll
            for (int nt = 0; nt < 8; ++nt) {
                float e0 = __expf(v[nt][0] - mx);
                float e1 = __expf(v[nt][1] - mx);
                sacc[mt][nt][hf * 2 + 0] = e0;
                sacc[mt][nt][hf * 2 + 1] = e1;
                sum += e0 + e1;
            }
            sum += __shfl_xor_sync(0xffffffffu, sum, 1);
            sum += __shfl_xor_sync(0xffffffffu, sum, 2);
            invr[mt][hf] = 1.f / sum;
        }
    }

    float o[2][4][4];
#pragma unroll
    for (int a = 0; a < 2; a++)
#pragma unroll
        for (int b = 0; b < 4; b++)
#pragma unroll
            for (int cse = 0; cse < 4; cse++) o[a][b][cse] = 0.f;

#pragma unroll
    for (int k2 = 0; k2 < 4; ++k2) {
        uint32_t pf[2][4];
#pragma unroll
        for (int mt = 0; mt < 2; ++mt) {
            pf[mt][0] = packbf(sacc[mt][2 * k2][0],     sacc[mt][2 * k2][1]);
            pf[mt][1] = packbf(sacc[mt][2 * k2][2],     sacc[mt][2 * k2][3]);
            pf[mt][2] = packbf(sacc[mt][2 * k2 + 1][0], sacc[mt][2 * k2 + 1][1]);
            pf[mt][3] = packbf(sacc[mt][2 * k2 + 1][2], sacc[mt][2 * k2 + 1][3]);
        }
#pragma unroll
        for (int ntd = 0; ntd < 4; ++ntd) {
            uint32_t bv[2];
            int d = ntd * 8 + gr;
            bv[0] = Vt[d * 36 + k2 * 8 + gc];
            bv[1] = Vt[d * 36 + k2 * 8 + gc + 4];
            mma_bf16(o[0][ntd], pf[0], bv);
            mma_bf16(o[1][ntd], pf[1], bv);
        }
    }

#pragma unroll
    for (int mt = 0; mt < 2; ++mt) {
#pragma unroll
        for (int hf = 0; hf < 2; ++hf) {
            int row = qb + mt * 16 + gr + hf * 8;
            if (row < Nn) {
                float iv = invr[mt][hf];
                bf16* op = g_ATT + ((size_t)(win * Nn + row)) * Cc + h * HDd;
#pragma unroll
                for (int ntd = 0; ntd < 4; ++ntd) {
                    *(uint32_t*)(op + ntd * 8 + 2 * gc) =
                        packbf(o[mt][ntd][hf * 2] * iv, o[mt][ntd][hf * 2 + 1] * iv);
                }
            }
        }
    }
}

// --------------------------- launch ------------------------------------------
extern "C" void kernel_launch(void* const* d_in, const int* in_sizes, int n_in,
                              void* d_out, int out_size) {
    const float* x        = (const float*)d_in[0];
    const float* norm1_g  = (const float*)d_in[1];
    const float* norm1_b  = (const float*)d_in[2];
    const float* qkv_w    = (const float*)d_in[3];
    const float* rel_bias = (const float*)d_in[4];
    const float* proj_w   = (const float*)d_in[5];
    const float* proj_b   = (const float*)d_in[6];
    const float* norm2_g  = (const float*)d_in[7];
    const float* norm2_b  = (const float*)d_in[8];
    const float* fc1_w    = (const float*)d_in[9];
    const float* fc1_b    = (const float*)d_in[10];
    const float* fc2_w    = (const float*)d_in[11];
    const float* fc2_b    = (const float*)d_in[12];
    float* out = (float*)d_out;

    bf16 *XW, *QKV, *ATT, *XN2, *Hb, *Wq, *Wp, *W1, *W2;
    float *XR;
    cudaGetSymbolAddress((void**)&XW,  g_XW);
    cudaGetSymbolAddress((void**)&QKV, g_QKV);
    cudaGetSymbolAddress((void**)&ATT, g_ATT);
    cudaGetSymbolAddress((void**)&XR,  g_XR);
    cudaGetSymbolAddress((void**)&XN2, g_XN2);
    cudaGetSymbolAddress((void**)&Hb,  g_H);
    cudaGetSymbolAddress((void**)&Wq,  g_Wq);
    cudaGetSymbolAddress((void**)&Wp,  g_Wp);
    cudaGetSymbolAddress((void**)&W1,  g_W1);
    cudaGetSymbolAddress((void**)&W2,  g_W2);

    cudaFuncSetAttribute(gemm_mma<0, 192>, cudaFuncAttributeMaxDynamicSharedMemorySize, GSMEM);
    cudaFuncSetAttribute(gemm_mma<1, 192>, cudaFuncAttributeMaxDynamicSharedMemorySize, GSMEM);
    cudaFuncSetAttribute(gemm_mma<2, 192>, cudaFuncAttributeMaxDynamicSharedMemorySize, GSMEM);
    cudaFuncSetAttribute(gemm_mma<3, 768>, cudaFuncAttributeMaxDynamicSharedMemorySize, GSMEM);
    cudaFuncSetAttribute(attn_mma_kernel, cudaFuncAttributeMaxDynamicSharedMemorySize, ATTN_SMEM_BYTES);

    // 0. weights -> bf16; bias+mask table
    wconv_kernel<<<(MLPH * Cc + 255) / 256, 256>>>(qkv_w, proj_w, fc1_w, fc2_w);
    bm_init_kernel<<<(4 * NHh * 64 * 64 + 255) / 256, 256>>>(rel_bias);
    // 1. LN1 + cyclic shift + window partition -> XW (bf16)
    ln1_gather_kernel<<<TOT / 8, 256>>>(x, norm1_g, norm1_b);
    // 2. QKV gemm -> QKV (bf16)
    gemm_mma<0, 192><<<dim3(TOT / GBM, 576 / GBN), 512, GSMEM>>>(
        XW, Wq, nullptr, nullptr, QKV, 3 * Cc, nullptr, nullptr);
    // 3. windowed attention (mma) -> ATT (bf16)
    attn_mma_kernel<<<NWIN, 384, ATTN_SMEM_BYTES>>>();
    // 4. proj + bias + reverse scatter + residual + LN2 -> XR (fp32) + XN2 (bf16)
    gemm_mma<1, 192><<<dim3(TOT / GBM, 1), 512, GSMEM>>>(
        ATT, Wp, proj_b, x, XR, Cc, norm2_g, norm2_b);
    // 5. FC1 + bias + exact GELU -> H (bf16)
    gemm_mma<2, 192><<<dim3(TOT / GBM, MLPH / GBN), 512, GSMEM>>>(
        XN2, W1, fc1_b, nullptr, Hb, MLPH, nullptr, nullptr);
    // 6. FC2 + bias + residual(XR) -> out (fp32)
    gemm_mma<3, 768><<<dim3(TOT / GBM, 1), 512, GSMEM>>>(
        Hb, W2, fc2_b, XR, out, Cc, nullptr, nullptr);
}

// round 13
// speedup vs baseline: 1.1298x; 1.1298x over previous
#include <cuda_runtime.h>
#include <cuda_bf16.h>
#include <math.h>
#include <stdint.h>

// ---------------------------------------------------------------------------
// Swin block: B=32,H=W=56,C=192,NH=6,WS=7,SS=3,HD=32,N=49,MLP_H=768
// GEMMs + attention via mma.sync m16n8k16 bf16, ldmatrix, cp.async.
// Round-9 GEMM config (BM128/BN64/BK64) + dedicated proj kernel fusing
// bias + reverse-shift scatter + residual + LayerNorm2.
// ---------------------------------------------------------------------------

#define Bn     32
#define Hh     56
#define Ww     56
#define Cc     192
#define NHh    6
#define WSs    7
#define SSs    3
#define HDd    32
#define Nn     49
#define MLPH   768
#define Ltok   (Hh*Ww)
#define TOT    (Bn*Ltok)          // 100352
#define NWIN   2048
#define SCALEF 0.17677669529663687f

// main GEMM tiling: CTA 128x64, K-chunk 64, 8 warps (4M x 2N), warp 32x32.
#define BM   128
#define BN   64
#define BK   64
#define PADE 72                   // row pitch in bf16 (144B)
#define ABUFE (BM*PADE)           // 9216
#define BBUFE (BN*PADE)           // 4608
#define SMEM_BYTES ((2*ABUFE + 2*BBUFE) * 2)   // 55296

// proj+LN kernel tiling: CTA 64x192 (full rows), 8 warps (2M x 4N), warp 32x48.
#define PBM   64
#define P_AST (PBM*PADE)          // 4608
#define P_BST (Cc*PADE)           // 13824
#define PSMEM ((2*P_AST + 2*P_BST) * 2)   // 73728

typedef __nv_bfloat16 bf16;
typedef __nv_bfloat162 bf162;

// ------------------------- scratch (device globals) ------------------------
__device__ bf16  g_XW [TOT * Cc];
__device__ bf16  g_QKV[TOT * 3 * Cc];
__device__ bf16  g_ATT[TOT * Cc];
__device__ float g_XR [TOT * Cc];
__device__ bf16  g_XN2[TOT * Cc];
__device__ bf16  g_H  [TOT * MLPH];
__device__ bf16  g_Wq [576 * Cc];
__device__ bf16  g_Wp [Cc * Cc];
__device__ bf16  g_W1 [MLPH * Cc];
__device__ bf16  g_W2 [Cc * MLPH];
__device__ float g_BM [4 * NHh * 64 * 64];

// --------------------------- PTX helpers -----------------------------------
__device__ __forceinline__ uint32_t smem_u32(const void* p) {
    uint32_t a;
    asm("{ .reg .u64 t; cvta.to.shared.u64 t, %1; cvt.u32.u64 %0, t; }"
        : "=r"(a) : "l"(p));
    return a;
}

#define CP_ASYNC16(dst, src) \
    asm volatile("cp.async.cg.shared.global [%0], [%1], 16;" :: "r"(dst), "l"(src))
#define CP_COMMIT() asm volatile("cp.async.commit_group;")
#define CP_WAIT(n)  asm volatile("cp.async.wait_group %0;" :: "n"(n))

__device__ __forceinline__ void mma_bf16(float* c, const uint32_t* a, const uint32_t* b) {
    asm volatile(
        "mma.sync.aligned.m16n8k16.row.col.f32.bf16.bf16.f32 "
        "{%0,%1,%2,%3}, {%4,%5,%6,%7}, {%8,%9}, {%0,%1,%2,%3};"
        : "+f"(c[0]), "+f"(c[1]), "+f"(c[2]), "+f"(c[3])
        : "r"(a[0]), "r"(a[1]), "r"(a[2]), "r"(a[3]), "r"(b[0]), "r"(b[1]));
}

__device__ __forceinline__ void ldsm_x4(uint32_t* r, uint32_t addr) {
    asm volatile("ldmatrix.sync.aligned.m8n8.x4.shared.b16 {%0,%1,%2,%3}, [%4];"
                 : "=r"(r[0]), "=r"(r[1]), "=r"(r[2]), "=r"(r[3]) : "r"(addr));
}

__device__ __forceinline__ uint32_t packbf(float lo, float hi) {
    uint32_t r;
    asm("cvt.rn.bf16x2.f32 %0, %1, %2;" : "=r"(r) : "f"(hi), "f"(lo));
    return r;
}

// --------------------- token <-> (shifted window) mapping ------------------
__device__ __forceinline__ int win_to_tok(int t) {
    int win = t / Nn, r = t - win * Nn;
    int b = win >> 6, w_ = win & 63;
    int wh = w_ >> 3, ww = w_ & 7;
    int ih = r / WSs, iw = r - ih * WSs;
    int rr = wh * WSs + ih + SSs; if (rr >= Hh) rr -= Hh;
    int cc = ww * WSs + iw + SSs; if (cc >= Ww) cc -= Ww;
    return b * Ltok + rr * Ww + cc;
}

// ----------------------- weight conversion to bf16 --------------------------
__global__ void wconv_kernel(const float* __restrict__ qw, const float* __restrict__ pw,
                             const float* __restrict__ w1, const float* __restrict__ w2) {
    int i = blockIdx.x * blockDim.x + threadIdx.x;
    if (i < 576 * Cc)  g_Wq[i] = __float2bfloat16(qw[i]);
    if (i < Cc * Cc)   g_Wp[i] = __float2bfloat16(pw[i]);
    if (i < MLPH * Cc) g_W1[i] = __float2bfloat16(w1[i]);
    if (i < Cc * MLPH) g_W2[i] = __float2bfloat16(w2[i]);
}

// -------------------- bias + shift-mask table init -------------------------
__global__ void bm_init_kernel(const float* __restrict__ tbl) {
    int idx = blockIdx.x * blockDim.x + threadIdx.x;
    if (idx >= 4 * NHh * 64 * 64) return;
    int j = idx & 63, i = (idx >> 6) & 63;
    int hh = (idx >> 12) % NHh, wt = (idx >> 12) / NHh;
    float v;
    if (i < Nn && j < Nn) {
        int ih = i / 7, iw = i % 7, jh = j / 7, jw = j % 7;
        int ridx = (ih - jh + 6) * 13 + (iw - jw + 6);
        v = tbl[ridx * NHh + hh];
        int th = wt >> 1, tw = wt & 1;
        int li = (th ? (ih < 4 ? 1 : 2) : 0) * 3 + (tw ? (iw < 4 ? 1 : 2) : 0);
        int lj = (th ? (jh < 4 ? 1 : 2) : 0) * 3 + (tw ? (jw < 4 ? 1 : 2) : 0);
        if (li != lj) v -= 100.f;
    } else {
        v = -1e30f;
    }
    g_BM[idx] = v;
}

// --------------------------- LN1 kernel -------------------------------------
__global__ void ln1_gather_kernel(const float* __restrict__ x,
                                  const float* __restrict__ g,
                                  const float* __restrict__ bt) {
    int warp = (blockIdx.x * blockDim.x + threadIdx.x) >> 5;
    int lane = threadIdx.x & 31;
    if (warp >= TOT) return;
    const float* src = x + (size_t)win_to_tok(warp) * Cc;
    float v[6], s = 0.f, ss = 0.f;
#pragma unroll
    for (int k = 0; k < 6; k++) { v[k] = src[lane + k * 32]; s += v[k]; ss += v[k] * v[k]; }
#pragma unroll
    for (int o = 16; o; o >>= 1) {
        s  += __shfl_xor_sync(0xffffffffu, s, o);
        ss += __shfl_xor_sync(0xffffffffu, ss, o);
    }
    float mu = s * (1.f / Cc);
    float rstd = rsqrtf(ss * (1.f / Cc) - mu * mu + 1e-5f);
    bf16* dst = g_XW + (size_t)warp * Cc;
#pragma unroll
    for (int k = 0; k < 6; k++) {
        int c = lane + k * 32;
        dst[c] = __float2bfloat16((v[k] - mu) * rstd * g[c] + bt[c]);
    }
}

// --------------------------- bf16 mma GEMM ----------------------------------
// C[M,Nd] = A[M,KK] * W[Nd,KK]^T.  CTA 128x64, 8 warps 4(M)x2(N), warp 32x32.
// ldmatrix.x4 fragment loads; cp.async double-buffered K-chunks of 64.
// EPI: 0 plain->bf16, 2 bias+gelu->bf16, 3 bias+residual->fp32.
template <int EPI, int KK>
__global__ __launch_bounds__(256)
void gemm_mma(const bf16* __restrict__ A, const bf16* __restrict__ W,
              const float* __restrict__ bias, const float* __restrict__ res,
              void* __restrict__ outp, int Nd) {
    constexpr int NC = KK / BK;
    extern __shared__ __align__(16) bf16 smem[];
    const uint32_t as_u[2] = {smem_u32(smem), smem_u32(smem + ABUFE)};
    const uint32_t bs_u[2] = {smem_u32(smem + 2 * ABUFE), smem_u32(smem + 2 * ABUFE + BBUFE)};

    const int tid = threadIdx.x;
    const int wid = tid >> 5;
    const int lane = tid & 31;
    const int gr = lane >> 2, gc = lane & 3;
    const int wm = wid >> 1;          // 0..3
    const int wn = wid & 1;           // 0..1
    const int mbase = blockIdx.x * BM;
    const int nbase = blockIdx.y * BN;

    const bf16* Ab = A + (size_t)mbase * KK;
    const bf16* Wb = W + (size_t)nbase * KK;

    const int rowA = wm * 32 + (lane & 15);
    const int colA = (lane >> 4) << 3;
    const int rowB = wn * 32 + (lane & 7) + ((lane >> 4) << 3);
    const int colB = ((lane >> 3) & 1) << 3;

    float acc[2][4][4];
#pragma unroll
    for (int i = 0; i < 2; i++)
#pragma unroll
        for (int j = 0; j < 4; j++)
#pragma unroll
            for (int k = 0; k < 4; k++) acc[i][j][k] = 0.f;

#pragma unroll
    for (int i = tid; i < BM * 8; i += 256) {
        int row = i >> 3, seg = i & 7;
        CP_ASYNC16(as_u[0] + (uint32_t)(row * 144 + seg * 16),
                   Ab + (size_t)row * KK + seg * 8);
    }
#pragma unroll
    for (int i = tid; i < BN * 8; i += 256) {
        int row = i >> 3, seg = i & 7;
        CP_ASYNC16(bs_u[0] + (uint32_t)(row * 144 + seg * 16),
                   Wb + (size_t)row * KK + seg * 8);
    }
    CP_COMMIT();

    for (int c = 0; c < NC; ++c) {
        if (c + 1 < NC) {
            const int nb = (c + 1) & 1;
            const int ko = (c + 1) * BK;
#pragma unroll
            for (int i = tid; i < BM * 8; i += 256) {
                int row = i >> 3, seg = i & 7;
                CP_ASYNC16(as_u[nb] + (uint32_t)(row * 144 + seg * 16),
                           Ab + (size_t)row * KK + ko + seg * 8);
            }
#pragma unroll
            for (int i = tid; i < BN * 8; i += 256) {
                int row = i >> 3, seg = i & 7;
                CP_ASYNC16(bs_u[nb] + (uint32_t)(row * 144 + seg * 16),
                           Wb + (size_t)row * KK + ko + seg * 8);
            }
            CP_COMMIT();
            CP_WAIT(1);
        } else {
            CP_WAIT(0);
        }
        __syncthreads();

        const uint32_t ab = as_u[c & 1];
        const uint32_t bb = bs_u[c & 1];
#pragma unroll
        for (int ks = 0; ks < 4; ++ks) {
            const int kk = ks * 16;
            uint32_t af[2][4], bq[2][4];
            ldsm_x4(af[0], ab + (uint32_t)(rowA * PADE + kk + colA) * 2);
            ldsm_x4(af[1], ab + (uint32_t)((rowA + 16) * PADE + kk + colA) * 2);
            ldsm_x4(bq[0], bb + (uint32_t)(rowB * PADE + kk + colB) * 2);
            ldsm_x4(bq[1], bb + (uint32_t)((rowB + 16) * PADE + kk + colB) * 2);
#pragma unroll
            for (int mt = 0; mt < 2; ++mt) {
                mma_bf16(acc[mt][0], af[mt], &bq[0][0]);
                mma_bf16(acc[mt][1], af[mt], &bq[0][2]);
                mma_bf16(acc[mt][2], af[mt], &bq[1][0]);
                mma_bf16(acc[mt][3], af[mt], &bq[1][2]);
            }
        }
        __syncthreads();
    }

    // ----------------------- fused epilogue ---------------------------------
#pragma unroll
    for (int mt = 0; mt < 2; ++mt) {
#pragma unroll
        for (int half = 0; half < 2; ++half) {
            int row = mbase + wm * 32 + mt * 16 + gr + half * 8;
#pragma unroll
            for (int nt = 0; nt < 4; ++nt) {
                int col = nbase + wn * 32 + nt * 8 + gc * 2;
                float v0 = acc[mt][nt][half * 2 + 0];
                float v1 = acc[mt][nt][half * 2 + 1];
                if (EPI == 0) {
                    *(uint32_t*)((bf16*)outp + (size_t)row * Nd + col) = packbf(v0, v1);
                } else if (EPI == 2) {
                    float a0 = v0 + bias[col], a1 = v1 + bias[col + 1];
                    const float kc = 0.70710678118654752f;
                    *(uint32_t*)((bf16*)outp + (size_t)row * Nd + col) =
                        packbf(0.5f * a0 * (1.f + erff(a0 * kc)),
                               0.5f * a1 * (1.f + erff(a1 * kc)));
                } else { // EPI == 3
                    const float* rp = res + (size_t)row * Nd + col;
                    float2 o = make_float2(v0 + bias[col] + rp[0],
                                           v1 + bias[col + 1] + rp[1]);
                    *(float2*)((float*)outp + (size_t)row * Nd + col) = o;
                }
            }
        }
    }
}

// ------------------- proj GEMM + bias + residual + LN2 ----------------------
// C[64,192] = ATT[64,192] * Wp[192,192]^T per CTA; epilogue: stage to smem,
// add residual x (scattered rows), LayerNorm, write XR (fp32) + XN2 (bf16).
// 8 warps: 2(M) x 4(N), warp tile 32x48.
__global__ __launch_bounds__(256, 2)
void projln_mma(const bf16* __restrict__ A, const bf16* __restrict__ W,
                const float* __restrict__ bias, const float* __restrict__ x,
                float* __restrict__ xr, bf16* __restrict__ xn2,
                const float* __restrict__ g2, const float* __restrict__ b2) {
    extern __shared__ __align__(16) bf16 smem[];
    const uint32_t as_u[2] = {smem_u32(smem), smem_u32(smem + P_AST)};
    const uint32_t bs_u[2] = {smem_u32(smem + 2 * P_AST), smem_u32(smem + 2 * P_AST + P_BST)};

    const int tid = threadIdx.x;
    const int wid = tid >> 5;
    const int lane = tid & 31;
    const int gr = lane >> 2, gc = lane & 3;
    const int wm = wid >> 2;          // 0..1 (32 rows each)
    const int wn = wid & 3;           // 0..3 (48 cols each)
    const int mbase = blockIdx.x * PBM;

    const bf16* Ab = A + (size_t)mbase * Cc;

    const int rowA = wm * 32 + (lane & 15);
    const int colA = (lane >> 4) << 3;
    const int rowB = wn * 48 + (lane & 7) + ((lane >> 4) << 3);
    const int colB = ((lane >> 3) & 1) << 3;

    float acc[2][6][4];
#pragma unroll
    for (int i = 0; i < 2; i++)
#pragma unroll
        for (int j = 0; j < 6; j++)
#pragma unroll
            for (int k = 0; k < 4; k++) acc[i][j][k] = 0.f;

    // prologue: chunk 0
#pragma unroll
    for (int i = tid; i < PBM * 8; i += 256) {
        int row = i >> 3, seg = i & 7;
        CP_ASYNC16(as_u[0] + (uint32_t)(row * 144 + seg * 16),
                   Ab + (size_t)row * Cc + seg * 8);
    }
#pragma unroll
    for (int i = tid; i < Cc * 8; i += 256) {
        int row = i >> 3, seg = i & 7;
        CP_ASYNC16(bs_u[0] + (uint32_t)(row * 144 + seg * 16),
                   W + (size_t)row * Cc + seg * 8);
    }
    CP_COMMIT();

    for (int c = 0; c < 3; ++c) {     // K = 192 = 3 x 64
        if (c + 1 < 3) {
            const int nb = (c + 1) & 1;
            const int ko = (c + 1) * BK;
#pragma unroll
            for (int i = tid; i < PBM * 8; i += 256) {
                int row = i >> 3, seg = i & 7;
                CP_ASYNC16(as_u[nb] + (uint32_t)(row * 144 + seg * 16),
                           Ab + (size_t)row * Cc + ko + seg * 8);
            }
#pragma unroll
            for (int i = tid; i < Cc * 8; i += 256) {
                int row = i >> 3, seg = i & 7;
                CP_ASYNC16(bs_u[nb] + (uint32_t)(row * 144 + seg * 16),
                           W + (size_t)row * Cc + ko + seg * 8);
            }
            CP_COMMIT();
            CP_WAIT(1);
        } else {
            CP_WAIT(0);
        }
        __syncthreads();

        const uint32_t ab = as_u[c & 1];
        const uint32_t bb = bs_u[c & 1];
#pragma unroll
        for (int ks = 0; ks < 4; ++ks) {
            const int kk = ks * 16;
            uint32_t af[2][4], bq[3][4];
            ldsm_x4(af[0], ab + (uint32_t)(rowA * PADE + kk + colA) * 2);
            ldsm_x4(af[1], ab + (uint32_t)((rowA + 16) * PADE + kk + colA) * 2);
#pragma unroll
            for (int nt2 = 0; nt2 < 3; ++nt2)
                ldsm_x4(bq[nt2], bb + (uint32_t)((rowB + nt2 * 16) * PADE + kk + colB) * 2);
#pragma unroll
            for (int mt = 0; mt < 2; ++mt)
#pragma unroll
                for (int nt2 = 0; nt2 < 3; ++nt2) {
                    mma_bf16(acc[mt][nt2 * 2 + 0], af[mt], &bq[nt2][0]);
                    mma_bf16(acc[mt][nt2 * 2 + 1], af[mt], &bq[nt2][2]);
                }
        }
        __syncthreads();
    }

    // ---- epilogue: stage + residual + LN2 ----
    float* stg = (float*)smem;        // 64 x 200 fp32 = 51200 B
#pragma unroll
    for (int mt = 0; mt < 2; ++mt)
#pragma unroll
        for (int half = 0; half < 2; ++half) {
            int r64 = wm * 32 + mt * 16 + gr + half * 8;
#pragma unroll
            for (int nj = 0; nj < 6; ++nj) {
                int col = wn * 48 + (nj >> 1) * 16 + (nj & 1) * 8 + gc * 2;
                stg[r64 * 200 + col]     = acc[mt][nj][half * 2]     + bias[col];
                stg[r64 * 200 + col + 1] = acc[mt][nj][half * 2 + 1] + bias[col + 1];
            }
        }
    __syncthreads();

#pragma unroll
    for (int it = 0; it < 8; ++it) {
        int r64 = wid * 8 + it;
        int tok = win_to_tok(mbase + r64);
        const float* xp = x + (size_t)tok * Cc;
        float v[6], s = 0.f, ss = 0.f;
#pragma unroll
        for (int k = 0; k < 6; ++k) {
            int ccol = lane + k * 32;
            v[k] = stg[r64 * 200 + ccol] + xp[ccol];
            s += v[k]; ss += v[k] * v[k];
        }
#pragma unroll
        for (int o = 16; o; o >>= 1) {
            s  += __shfl_xor_sync(0xffffffffu, s, o);
            ss += __shfl_xor_sync(0xffffffffu, ss, o);
        }
        float mu = s * (1.f / Cc);
        float rstd = rsqrtf(ss * (1.f / Cc) - mu * mu + 1e-5f);
        float* xrow = xr + (size_t)tok * Cc;
        bf16* nrow = xn2 + (size_t)tok * Cc;
#pragma unroll
        for (int k = 0; k < 6; ++k) {
            int ccol = lane + k * 32;
            xrow[ccol] = v[k];
            nrow[ccol] = __float2bfloat16((v[k] - mu) * rstd * g2[ccol] + b2[ccol]);
        }
    }
}

// --------------------------- mma attention ----------------------------------
#define ATTN_SMEM_BYTES (6 * 3712 * 4)   // 89088

__global__ __launch_bounds__(384, 1)
void attn_mma_kernel() {
    extern __shared__ uint32_t sm32[];
    const int tid = threadIdx.x;
    const int win = blockIdx.x;
    const int h = tid >> 6;
    const int t2 = tid & 63;

    uint32_t* Qs = sm32 + h * 3712;
    uint32_t* Ks = Qs + 1280;
    uint32_t* Vt = Ks + 1280;

    for (int i = t2; i < 3712; i += 64) Qs[i] = 0;
    __syncthreads();

    const uint32_t* qkv = (const uint32_t*)g_QKV + (size_t)win * Nn * 288;
    bf16* vtb = (bf16*)Vt;
    for (int i = t2; i < Nn * 16; i += 64) {
        int row = i >> 4, wd = i & 15;
        const uint32_t* tp = qkv + row * 288 + h * 16 + wd;
        Qs[row * 20 + wd] = tp[0];
        Ks[row * 20 + wd] = tp[96];
        uint32_t vv = tp[192];
        bf162 v2 = *(bf162*)&vv;
        vtb[(2 * wd) * 72 + row]     = v2.x;
        vtb[(2 * wd + 1) * 72 + row] = v2.y;
    }
    __syncthreads();

    const int w = tid >> 5;
    const int lane = tid & 31;
    const int gr = lane >> 2, gc = lane & 3;
    const int qb = (w & 1) * 32;
    const int wh = (win & 63) >> 3, ww = win & 7;
    const int wt = ((wh == 7) ? 2 : 0) + ((ww == 7) ? 1 : 0);
    const float* bmp = g_BM + ((size_t)(wt * NHh + h) << 12);

    float sacc[2][8][4];
#pragma unroll
    for (int a = 0; a < 2; a++)
#pragma unroll
        for (int b = 0; b < 8; b++)
#pragma unroll
            for (int cse = 0; cse < 4; cse++) sacc[a][b][cse] = 0.f;

#pragma unroll
    for (int kst = 0; kst < 2; ++kst) {
        uint32_t af[2][4], bfr[8][2];
#pragma unroll
        for (int mt = 0; mt < 2; ++mt) {
            int r = qb + mt * 16 + gr;
            af[mt][0] = Qs[r * 20 + kst * 8 + gc];
            af[mt][1] = Qs[(r + 8) * 20 + kst * 8 + gc];
            af[mt][2] = Qs[r * 20 + kst * 8 + gc + 4];
            af[mt][3] = Qs[(r + 8) * 20 + kst * 8 + gc + 4];
        }
#pragma unroll
        for (int nt = 0; nt < 8; ++nt) {
            int j = nt * 8 + gr;
            bfr[nt][0] = Ks[j * 20 + kst * 8 + gc];
            bfr[nt][1] = Ks[j * 20 + kst * 8 + gc + 4];
        }
#pragma unroll
        for (int mt = 0; mt < 2; ++mt)
#pragma unroll
            for (int nt = 0; nt < 8; ++nt)
                mma_bf16(sacc[mt][nt], af[mt], bfr[nt]);
    }

    float invr[2][2];
#pragma unroll
    for (int mt = 0; mt < 2; ++mt) {
#pragma unroll
        for (int hf = 0; hf < 2; ++hf) {
            int row = qb + mt * 16 + gr + hf * 8;
            const float* bmr = bmp + row * 64 + 2 * gc;
            float v[8][2], mx = -3e38f;
#pragma unroll
            for (int nt = 0; nt < 8; ++nt) {
                float2 bm2 = *(const float2*)(bmr + nt * 8);
                v[nt][0] = sacc[mt][nt][hf * 2 + 0] * SCALEF + bm2.x;
                v[nt][1] = sacc[mt][nt][hf * 2 + 1] * SCALEF + bm2.y;
                mx = fmaxf(mx, fmaxf(v[nt][0], v[nt][1]));
            }
            mx = fmaxf(mx, __shfl_xor_sync(0xffffffffu, mx, 1));
            mx = fmaxf(mx, __shfl_xor_sync(0xffffffffu, mx, 2));
            float sum = 0.f;
#pragma unroll
            for (int nt = 0; nt < 8; ++nt) {
                float e0 = __expf(v[nt][0] - mx);
                float e1 = __expf(v[nt][1] - mx);
                sacc[mt][nt][hf * 2 + 0] = e0;
                sacc[mt][nt][hf * 2 + 1] = e1;
                sum += e0 + e1;
            }
            sum += __shfl_xor_sync(0xffffffffu, sum, 1);
            sum += __shfl_xor_sync(0xffffffffu, sum, 2);
            invr[mt][hf] = 1.f / sum;
        }
    }

    float o[2][4][4];
#pragma unroll
    for (int a = 0; a < 2; a++)
#pragma unroll
        for (int b = 0; b < 4; b++)
#pragma unroll
            for (int cse = 0; cse < 4; cse++) o[a][b][cse] = 0.f;

#pragma unroll
    for (int k2 = 0; k2 < 4; ++k2) {
        uint32_t pf[2][4];
#pragma unroll
        for (int mt = 0; mt < 2; ++mt) {
            pf[mt][0] = packbf(sacc[mt][2 * k2][0],     sacc[mt][2 * k2][1]);
            pf[mt][1] = packbf(sacc[mt][2 * k2][2],     sacc[mt][2 * k2][3]);
            pf[mt][2] = packbf(sacc[mt][2 * k2 + 1][0], sacc[mt][2 * k2 + 1][1]);
            pf[mt][3] = packbf(sacc[mt][2 * k2 + 1][2], sacc[mt][2 * k2 + 1][3]);
        }
#pragma unroll
        for (int ntd = 0; ntd < 4; ++ntd) {
            uint32_t bv[2];
            int d = ntd * 8 + gr;
            bv[0] = Vt[d * 36 + k2 * 8 + gc];
            bv[1] = Vt[d * 36 + k2 * 8 + gc + 4];
            mma_bf16(o[0][ntd], pf[0], bv);
            mma_bf16(o[1][ntd], pf[1], bv);
        }
    }

#pragma unroll
    for (int mt = 0; mt < 2; ++mt) {
#pragma unroll
        for (int hf = 0; hf < 2; ++hf) {
            int row = qb + mt * 16 + gr + hf * 8;
            if (row < Nn) {
                float iv = invr[mt][hf];
                bf16* op = g_ATT + ((size_t)(win * Nn + row)) * Cc + h * HDd;
#pragma unroll
                for (int ntd = 0; ntd < 4; ++ntd) {
                    *(uint32_t*)(op + ntd * 8 + 2 * gc) =
                        packbf(o[mt][ntd][hf * 2] * iv, o[mt][ntd][hf * 2 + 1] * iv);
                }
            }
        }
    }
}

// --------------------------- launch ------------------------------------------
extern "C" void kernel_launch(void* const* d_in, const int* in_sizes, int n_in,
                              void* d_out, int out_size) {
    const float* x        = (const float*)d_in[0];
    const float* norm1_g  = (const float*)d_in[1];
    const float* norm1_b  = (const float*)d_in[2];
    const float* qkv_w    = (const float*)d_in[3];
    const float* rel_bias = (const float*)d_in[4];
    const float* proj_w   = (const float*)d_in[5];
    const float* proj_b   = (const float*)d_in[6];
    const float* norm2_g  = (const float*)d_in[7];
    const float* norm2_b  = (const float*)d_in[8];
    const float* fc1_w    = (const float*)d_in[9];
    const float* fc1_b    = (const float*)d_in[10];
    const float* fc2_w    = (const float*)d_in[11];
    const float* fc2_b    = (const float*)d_in[12];
    float* out = (float*)d_out;

    bf16 *XW, *QKV, *ATT, *XN2, *Hb, *Wq, *Wp, *W1, *W2;
    float *XR;
    cudaGetSymbolAddress((void**)&XW,  g_XW);
    cudaGetSymbolAddress((void**)&QKV, g_QKV);
    cudaGetSymbolAddress((void**)&ATT, g_ATT);
    cudaGetSymbolAddress((void**)&XR,  g_XR);
    cudaGetSymbolAddress((void**)&XN2, g_XN2);
    cudaGetSymbolAddress((void**)&Hb,  g_H);
    cudaGetSymbolAddress((void**)&Wq,  g_Wq);
    cudaGetSymbolAddress((void**)&Wp,  g_Wp);
    cudaGetSymbolAddress((void**)&W1,  g_W1);
    cudaGetSymbolAddress((void**)&W2,  g_W2);

    cudaFuncSetAttribute(gemm_mma<0, 192>, cudaFuncAttributeMaxDynamicSharedMemorySize, SMEM_BYTES);
    cudaFuncSetAttribute(gemm_mma<2, 192>, cudaFuncAttributeMaxDynamicSharedMemorySize, SMEM_BYTES);
    cudaFuncSetAttribute(gemm_mma<3, 768>, cudaFuncAttributeMaxDynamicSharedMemorySize, SMEM_BYTES);
    cudaFuncSetAttribute(projln_mma, cudaFuncAttributeMaxDynamicSharedMemorySize, PSMEM);
    cudaFuncSetAttribute(attn_mma_kernel, cudaFuncAttributeMaxDynamicSharedMemorySize, ATTN_SMEM_BYTES);

    // 0. weights -> bf16; bias+mask table
    wconv_kernel<<<(MLPH * Cc + 255) / 256, 256>>>(qkv_w, proj_w, fc1_w, fc2_w);
    bm_init_kernel<<<(4 * NHh * 64 * 64 + 255) / 256, 256>>>(rel_bias);
    // 1. LN1 + cyclic shift + window partition -> XW (bf16)
    ln1_gather_kernel<<<TOT / 8, 256>>>(x, norm1_g, norm1_b);
    // 2. QKV gemm -> QKV (bf16)
    gemm_mma<0, 192><<<dim3(TOT / BM, 576 / BN), 256, SMEM_BYTES>>>(
        XW, Wq, nullptr, nullptr, QKV, 3 * Cc);
    // 3. windowed attention (mma) -> ATT (bf16)
    attn_mma_kernel<<<NWIN, 384, ATTN_SMEM_BYTES>>>();
    // 4. proj + bias + reverse scatter + residual + LN2 -> XR (fp32) + XN2 (bf16)
    projln_mma<<<TOT / PBM, 256, PSMEM>>>(ATT, Wp, proj_b, x, XR, XN2,
                                          norm2_g, norm2_b);
    // 5. FC1 + bias + exact GELU -> H (bf16)
    gemm_mma<2, 192><<<dim3(TOT / BM, MLPH / BN), 256, SMEM_BYTES>>>(
        XN2, W1, fc1_b, nullptr, Hb, MLPH);
    // 6. FC2 + bias + residual(XR) -> out (fp32)
    gemm_mma<3, 768><<<dim3(TOT / BM, Cc / BN), 256, SMEM_BYTES>>>(
        Hb, W2, fc2_b, XR, out, Cc);
}